// round 4
// baseline (speedup 1.0000x reference)
#include <cuda_runtime.h>
#include <cstddef>

#define Hd 10
#define Td 20
#define M1 5

using u64 = unsigned long long;

// ---- f32x2 packed helpers (sm_100+) ----
__device__ __forceinline__ u64 pack2(float lo, float hi) {
    u64 r; asm("mov.b64 %0, {%1, %2};" : "=l"(r) : "f"(lo), "f"(hi)); return r;
}
__device__ __forceinline__ void unpack2(u64 v, float &lo, float &hi) {
    asm("mov.b64 {%0, %1}, %2;" : "=f"(lo), "=f"(hi) : "l"(v));
}
__device__ __forceinline__ void fma2(u64 &d, u64 a, u64 b) {
    asm("fma.rn.f32x2 %0, %1, %2, %0;" : "+l"(d) : "l"(a), "l"(b));
}
__device__ __forceinline__ u64 fma2_3(u64 a, u64 b, u64 c) {
    u64 d; asm("fma.rn.f32x2 %0, %1, %2, %3;" : "=l"(d) : "l"(a), "l"(b), "l"(c)); return d;
}

// ---- activations ----
__device__ __forceinline__ float tanh_fast(float x) {
    float r; asm("tanh.approx.f32 %0, %1;" : "=f"(r) : "f"(x)); return r;
}
__device__ __forceinline__ float sig_fast(float x) {
    return fmaf(tanh_fast(0.5f * x), 0.5f, 0.5f);
}
__device__ __forceinline__ float sig_acc(float x) {
    return __fdividef(1.0f, 1.0f + __expf(-x));
}

__global__ void __launch_bounds__(128, 6)
lstm_disc_kernel(const float* __restrict__ values,
                 const float* __restrict__ masks,
                 const float* __restrict__ W_ih,   // (40,1)
                 const float* __restrict__ W_hh,   // (40,10) row-major
                 const float* __restrict__ b_ih,   // (40)
                 const float* __restrict__ b_hh,   // (40)
                 const float* __restrict__ W1,     // (5,10)
                 const float* __restrict__ b1,     // (5)
                 const float* __restrict__ W2,     // (1,5)
                 const float* __restrict__ b2,     // (1)
                 float* __restrict__ out,          // scores (B,T) then masks (B,T)
                 int B)
{
    // Gate-pair packed layouts. For lane-pair p (lanes 2p,2p+1) and h-index k:
    // sWg[p][k] = { Wi[2p],Wi[2p+1], Wf[2p],Wf[2p+1], Wg[2p],Wg[2p+1], Wo[2p],Wo[2p+1] }[k]
    __shared__ __align__(16) float sWg[5][Hd][8];
    // sBX[p][0..7] = bias pairs (same gate order), sBX[p][8..15] = W_ih pairs
    __shared__ __align__(16) float sBX[5][16];
    __shared__ __align__(8)  float2 sW1p[M1][M1];  // (W1[j][2q], W1[j][2q+1])
    __shared__ __align__(8)  float2 sB1p[M1];      // (b1[j], 0)
    __shared__ float sW2[M1];
    __shared__ float sB2;

    const int tid = threadIdx.x;
    for (int i = tid; i < 5 * Hd * 8; i += blockDim.x) {
        int p = i / 80, r = i % 80, k = r / 8, g = r % 8;
        int j = (g >> 1) * 10 + 2 * p + (g & 1);   // gate row index in [0,40)
        sWg[p][k][g] = W_hh[j * Hd + k];
    }
    if (tid < 80) {
        int p = tid / 16, r = tid % 16;
        int g = (r < 8) ? r : r - 8;
        int j = (g >> 1) * 10 + 2 * p + (g & 1);
        sBX[p][r] = (r < 8) ? (b_ih[j] + b_hh[j]) : W_ih[j];
    }
    if (tid < M1 * M1) {
        int j = tid / M1, q = tid % M1;
        sW1p[j][q] = make_float2(W1[j * Hd + 2 * q], W1[j * Hd + 2 * q + 1]);
    }
    if (tid < M1) { sB1p[tid] = make_float2(b1[tid], 0.0f); sW2[tid] = W2[tid]; }
    if (tid == 0) sB2 = b2[0];
    __syncthreads();

    const int b = blockIdx.x * blockDim.x + tid;
    if (b >= B) return;

    const float* __restrict__ vrow = values + (size_t)b * Td;
    float* __restrict__ srow = out + (size_t)b * Td;

    float h[Hd], c[Hd];
#pragma unroll
    for (int k = 0; k < Hd; k++) { h[k] = 0.f; c[k] = 0.f; }

#pragma unroll 1
    for (int t = 0; t < Td; t++) {
        // ---- MLP scoring head on pre-update h ----
        u64 hp[M1];
#pragma unroll
        for (int q = 0; q < M1; q++) hp[q] = pack2(h[2 * q], h[2 * q + 1]);

        float acc = sB2;
#pragma unroll
        for (int j = 0; j < M1; j++) {
            u64 a2 = *(const u64*)&sB1p[j];
#pragma unroll
            for (int q = 0; q < M1; q++) {
                const u64 w = *(const u64*)&sW1p[j][q];
                fma2(a2, hp[q], w);
            }
            float lo, hi; unpack2(a2, lo, hi);
            float z = lo + hi;
            z = fmaxf(z, 0.2f * z);              // leaky_relu(0.2)
            acc = fmaf(sW2[j], z, acc);
        }
        srow[t] = sig_acc(acc);

        // ---- LSTM gates, p-block at a time (4 u64 accumulators live) ----
        const float x = vrow[t];
        const u64 xp = pack2(x, x);
        float hn[Hd];
#pragma unroll
        for (int p = 0; p < 5; p++) {
            const ulonglong2* __restrict__ bx = (const ulonglong2*)sBX[p];
            const ulonglong2 bA = bx[0], bB = bx[1], wA = bx[2], wB = bx[3];
            u64 aI = fma2_3(xp, wA.x, bA.x);
            u64 aF = fma2_3(xp, wA.y, bA.y);
            u64 aG = fma2_3(xp, wB.x, bB.x);
            u64 aO = fma2_3(xp, wB.y, bB.y);

            const ulonglong2* __restrict__ wg = (const ulonglong2*)&sWg[p][0][0];
#pragma unroll
            for (int k = 0; k < Hd; k++) {
                const ulonglong2 wIF = wg[2 * k];      // LDS.128: i-pair, f-pair
                const ulonglong2 wGO = wg[2 * k + 1];  // LDS.128: g-pair, o-pair
                const u64 hk = pack2(h[k], h[k]);
                fma2(aI, hk, wIF.x); fma2(aF, hk, wIF.y);
                fma2(aG, hk, wGO.x); fma2(aO, hk, wGO.y);
            }

            float ia, ib, fa, fb, ga, gb, oa, ob;
            unpack2(aI, ia, ib); unpack2(aF, fa, fb);
            unpack2(aG, ga, gb); unpack2(aO, oa, ob);
            const float cnA = fmaf(sig_fast(fa), c[2 * p],     sig_fast(ia) * tanh_fast(ga));
            const float cnB = fmaf(sig_fast(fb), c[2 * p + 1], sig_fast(ib) * tanh_fast(gb));
            c[2 * p] = cnA; c[2 * p + 1] = cnB;
            hn[2 * p]     = sig_fast(oa) * tanh_fast(cnA);
            hn[2 * p + 1] = sig_fast(ob) * tanh_fast(cnB);
        }
#pragma unroll
        for (int k = 0; k < Hd; k++) h[k] = hn[k];
    }

    // ---- masks passthrough: one row = 20 floats = 5 float4 ----
    const float4* __restrict__ m0 = (const float4*)(masks + (size_t)b * Td);
    float4* __restrict__ mo = (float4*)(out + (size_t)B * Td + (size_t)b * Td);
#pragma unroll
    for (int q = 0; q < Td / 4; q++) mo[q] = m0[q];
}

extern "C" void kernel_launch(void* const* d_in, const int* in_sizes, int n_in,
                              void* d_out, int out_size)
{
    const float* values = (const float*)d_in[0];
    const float* masks  = (const float*)d_in[1];
    const float* W_ih   = (const float*)d_in[2];
    const float* W_hh   = (const float*)d_in[3];
    const float* b_ih   = (const float*)d_in[4];
    const float* b_hh   = (const float*)d_in[5];
    const float* W1     = (const float*)d_in[6];
    const float* b1     = (const float*)d_in[7];
    const float* W2     = (const float*)d_in[8];
    const float* b2     = (const float*)d_in[9];

    const int BT = in_sizes[0];          // B*T
    const int B  = BT / Td;
    float* out = (float*)d_out;

    lstm_disc_kernel<<<(B + 127) / 128, 128>>>(
        values, masks, W_ih, W_hh, b_ih, b_hh, W1, b1, W2, b2, out, B);
}

// round 5
// speedup vs baseline: 1.2466x; 1.2466x over previous
#include <cuda_runtime.h>
#include <cstddef>

#define Hd 10
#define Td 20
#define G4 40   // 4*Hd
#define M1 5    // MLP hidden

using u64 = unsigned long long;

// ---- f32x2 packed helpers (sm_100+) ----
__device__ __forceinline__ u64 pack2(float lo, float hi) {
    u64 r; asm("mov.b64 %0, {%1, %2};" : "=l"(r) : "f"(lo), "f"(hi)); return r;
}
__device__ __forceinline__ void unpack2(u64 v, float &lo, float &hi) {
    asm("mov.b64 {%0, %1}, %2;" : "=f"(lo), "=f"(hi) : "l"(v));
}
__device__ __forceinline__ void fma2(u64 &d, u64 a, u64 b) {
    asm("fma.rn.f32x2 %0, %1, %2, %0;" : "+l"(d) : "l"(a), "l"(b));
}
__device__ __forceinline__ u64 fma2_3(u64 a, u64 b, u64 c) {
    u64 d; asm("fma.rn.f32x2 %0, %1, %2, %3;" : "=l"(d) : "l"(a), "l"(b), "l"(c)); return d;
}

// ---- activations ----
__device__ __forceinline__ float tanh_fast(float x) {
    float r; asm("tanh.approx.f32 %0, %1;" : "=f"(r) : "f"(x)); return r;
}
__device__ __forceinline__ float sig_fast(float x) {
    return fmaf(tanh_fast(0.5f * x), 0.5f, 0.5f);   // 1 MUFU
}
__device__ __forceinline__ float sig_acc(float x) {  // accurate, for final score
    return __fdividef(1.0f, 1.0f + __expf(-x));
}

__global__ void __launch_bounds__(128, 4)
lstm_disc_kernel(const float* __restrict__ values,
                 const float* __restrict__ masks,
                 const float* __restrict__ W_ih,   // (40,1)
                 const float* __restrict__ W_hh,   // (40,10)
                 const float* __restrict__ b_ih,   // (40)
                 const float* __restrict__ b_hh,   // (40)
                 const float* __restrict__ W1,     // (5,10)
                 const float* __restrict__ b1,     // (5)
                 const float* __restrict__ W2,     // (1,5)
                 const float* __restrict__ b2,     // (1)
                 float* __restrict__ out,          // scores (B,T) then masks (B,T)
                 int B)
{
    // Weight staging in shared; per-step accesses are warp-uniform broadcasts
    // (no bank penalty), read as LDS.128 / LDS.64 vectors.
    __shared__ __align__(16) float sWt[Hd][G4];   // sWt[k][j] = W_hh[j][k]
    __shared__ __align__(16) float sWx[G4];       // W_ih[:,0]
    __shared__ __align__(16) float sB[G4];        // b_ih + b_hh
    __shared__ __align__(8)  float2 sW1p[M1][M1]; // (W1[j][2q], W1[j][2q+1])
    __shared__ __align__(8)  float2 sB1p[M1];     // (b1[j], 0)
    __shared__ float sW2[M1];
    __shared__ float sB2;

    const int tid = threadIdx.x;
    for (int i = tid; i < G4 * Hd; i += blockDim.x) {
        int j = i / Hd, k = i % Hd;
        sWt[k][j] = W_hh[i];
    }
    if (tid < G4) {
        sWx[tid] = W_ih[tid];
        sB[tid]  = b_ih[tid] + b_hh[tid];
    }
    if (tid < M1 * M1) {
        int j = tid / M1, q = tid % M1;
        sW1p[j][q] = make_float2(W1[j * Hd + 2 * q], W1[j * Hd + 2 * q + 1]);
    }
    if (tid < M1) { sB1p[tid] = make_float2(b1[tid], 0.0f); sW2[tid] = W2[tid]; }
    if (tid == 0) sB2 = b2[0];
    __syncthreads();

    const int b = blockIdx.x * blockDim.x + tid;
    if (b >= B) return;

    float h[Hd], c[Hd];
#pragma unroll
    for (int k = 0; k < Hd; k++) { h[k] = 0.0f; c[k] = 0.0f; }

    const float* __restrict__ vrow = values + (size_t)b * Td;
    float* __restrict__ srow = out + (size_t)b * Td;

#pragma unroll 1
    for (int t = 0; t < Td; t++) {
        // ---- MLP scoring head on pre-update h (packed f32x2) ----
        u64 hp[M1];
#pragma unroll
        for (int q = 0; q < M1; q++) hp[q] = pack2(h[2 * q], h[2 * q + 1]);

        float acc = sB2;
#pragma unroll
        for (int j = 0; j < M1; j++) {
            u64 a2 = *reinterpret_cast<const u64*>(&sB1p[j]);
#pragma unroll
            for (int q = 0; q < M1; q++) {
                const u64 w = *reinterpret_cast<const u64*>(&sW1p[j][q]);
                fma2(a2, hp[q], w);
            }
            float lo, hi; unpack2(a2, lo, hi);
            float z = lo + hi;
            z = fmaxf(z, 0.2f * z);              // leaky_relu(0.2)
            acc = fmaf(sW2[j], z, acc);
        }
        srow[t] = sig_acc(acc);

        // ---- LSTM gates: g = x*Wx + b + h @ Whh^T (packed f32x2) ----
        const float x = vrow[t];
        const u64 x2 = pack2(x, x);
        u64 g2[G4 / 2];
        const ulonglong2* __restrict__ wxr = reinterpret_cast<const ulonglong2*>(sWx);
        const ulonglong2* __restrict__ bbr = reinterpret_cast<const ulonglong2*>(sB);
#pragma unroll
        for (int q = 0; q < 10; q++) {
            ulonglong2 w  = wxr[q];              // LDS.128 -> 2 f32x2
            ulonglong2 bb = bbr[q];
            g2[2 * q]     = fma2_3(x2, w.x, bb.x);
            g2[2 * q + 1] = fma2_3(x2, w.y, bb.y);
        }
#pragma unroll
        for (int k = 0; k < Hd; k++) {
            const u64 hk2 = pack2(h[k], h[k]);
            const ulonglong2* __restrict__ row = reinterpret_cast<const ulonglong2*>(sWt[k]);
#pragma unroll
            for (int q = 0; q < 10; q++) {
                ulonglong2 w = row[q];           // LDS.128 -> 2 f32x2 -> 4 FMAs
                fma2(g2[2 * q],     hk2, w.x);
                fma2(g2[2 * q + 1], hk2, w.y);
            }
        }

        // ---- activations + state update (in-place, all gates already computed) ----
#pragma unroll
        for (int p = 0; p < 5; p++) {
            float i0, i1, f0, f1, gg0, gg1, o0, o1;
            unpack2(g2[p],      i0,  i1);
            unpack2(g2[p + 5],  f0,  f1);
            unpack2(g2[p + 10], gg0, gg1);
            unpack2(g2[p + 15], o0,  o1);
            const int u0 = 2 * p, u1 = 2 * p + 1;

            const float cn0 = fmaf(sig_fast(f0), c[u0], sig_fast(i0) * tanh_fast(gg0));
            const float cn1 = fmaf(sig_fast(f1), c[u1], sig_fast(i1) * tanh_fast(gg1));
            c[u0] = cn0; c[u1] = cn1;
            h[u0] = sig_fast(o0) * tanh_fast(cn0);
            h[u1] = sig_fast(o1) * tanh_fast(cn1);
        }
    }

    // ---- masks passthrough (fused; 5x float4 per thread) ----
    const float4* __restrict__ mrow = reinterpret_cast<const float4*>(masks + (size_t)b * Td);
    float4* __restrict__ morow = reinterpret_cast<float4*>(out + (size_t)B * Td + (size_t)b * Td);
#pragma unroll
    for (int q = 0; q < Td / 4; q++) morow[q] = mrow[q];
}

extern "C" void kernel_launch(void* const* d_in, const int* in_sizes, int n_in,
                              void* d_out, int out_size)
{
    const float* values = (const float*)d_in[0];
    const float* masks  = (const float*)d_in[1];
    const float* W_ih   = (const float*)d_in[2];
    const float* W_hh   = (const float*)d_in[3];
    const float* b_ih   = (const float*)d_in[4];
    const float* b_hh   = (const float*)d_in[5];
    const float* W1     = (const float*)d_in[6];
    const float* b1     = (const float*)d_in[7];
    const float* W2     = (const float*)d_in[8];
    const float* b2     = (const float*)d_in[9];

    const int BT = in_sizes[0];          // B*T
    const int B  = BT / Td;
    float* out = (float*)d_out;

    lstm_disc_kernel<<<(B + 127) / 128, 128>>>(
        values, masks, W_ih, W_hh, b_ih, b_hh, W1, b1, W2, b2, out, B);
}

// round 6
// speedup vs baseline: 1.2986x; 1.0417x over previous
#include <cuda_runtime.h>
#include <cstddef>

#define Hd 10
#define Td 20
#define M1 5

using u64 = unsigned long long;

// ---- f32x2 packed helpers (sm_100+) ----
__device__ __forceinline__ u64 pack2(float lo, float hi) {
    u64 r; asm("mov.b64 %0, {%1, %2};" : "=l"(r) : "f"(lo), "f"(hi)); return r;
}
__device__ __forceinline__ void unpack2(u64 v, float &lo, float &hi) {
    asm("mov.b64 {%0, %1}, %2;" : "=f"(lo), "=f"(hi) : "l"(v));
}
__device__ __forceinline__ void fma2(u64 &d, u64 a, u64 b) {
    asm("fma.rn.f32x2 %0, %1, %2, %0;" : "+l"(d) : "l"(a), "l"(b));
}
__device__ __forceinline__ u64 fma2_3(u64 a, u64 b, u64 c) {
    u64 d; asm("fma.rn.f32x2 %0, %1, %2, %3;" : "=l"(d) : "l"(a), "l"(b), "l"(c)); return d;
}

// ---- activations ----
__device__ __forceinline__ float tanh_fast(float x) {
    float r; asm("tanh.approx.f32 %0, %1;" : "=f"(r) : "f"(x)); return r;
}
__device__ __forceinline__ float sig_fast(float x) {
    return fmaf(tanh_fast(0.5f * x), 0.5f, 0.5f);   // 1 MUFU
}
__device__ __forceinline__ float sig_acc(float x) {  // accurate, for final score
    return __fdividef(1.0f, 1.0f + __expf(-x));
}

__global__ void __launch_bounds__(128, 4)
lstm_disc_kernel(const float* __restrict__ values,
                 const float* __restrict__ masks,
                 const float* __restrict__ W_ih,   // (40,1)
                 const float* __restrict__ W_hh,   // (40,10) row-major
                 const float* __restrict__ b_ih,   // (40)
                 const float* __restrict__ b_hh,   // (40)
                 const float* __restrict__ W1,     // (5,10)
                 const float* __restrict__ b1,     // (5)
                 const float* __restrict__ W2,     // (1,5)
                 const float* __restrict__ b2,     // (1)
                 float* __restrict__ out,          // scores (B,T) then masks (B,T)
                 int B)
{
    // Gate-pair packed layouts. For lane-pair p (lanes 2p,2p+1) and h-index k:
    // sWg[p][k] = { Wi[2p],Wi[2p+1], Wf[2p],Wf[2p+1], Wg[2p],Wg[2p+1], Wo[2p],Wo[2p+1] }[k]
    __shared__ __align__(16) float sWg[5][Hd][8];
    // sBX[p][0..7] = bias pairs (same gate order), sBX[p][8..15] = W_ih pairs
    __shared__ __align__(16) float sBX[5][16];
    __shared__ __align__(8)  float2 sW1p[M1][M1];  // (W1[j][2q], W1[j][2q+1])
    __shared__ __align__(8)  float2 sB1p[M1];      // (b1[j], 0)
    __shared__ float sW2[M1];
    __shared__ float sB2;

    const int tid = threadIdx.x;
    for (int i = tid; i < 5 * Hd * 8; i += blockDim.x) {
        int p = i / 80, r = i % 80, k = r / 8, g = r % 8;
        int j = (g >> 1) * 10 + 2 * p + (g & 1);   // gate row index in [0,40)
        sWg[p][k][g] = W_hh[j * Hd + k];
    }
    if (tid < 80) {
        int p = tid / 16, r = tid % 16;
        int g = (r < 8) ? r : r - 8;
        int j = (g >> 1) * 10 + 2 * p + (g & 1);
        sBX[p][r] = (r < 8) ? (b_ih[j] + b_hh[j]) : W_ih[j];
    }
    if (tid < M1 * M1) {
        int j = tid / M1, q = tid % M1;
        sW1p[j][q] = make_float2(W1[j * Hd + 2 * q], W1[j * Hd + 2 * q + 1]);
    }
    if (tid < M1) { sB1p[tid] = make_float2(b1[tid], 0.0f); sW2[tid] = W2[tid]; }
    if (tid == 0) sB2 = b2[0];
    __syncthreads();

    const int b = blockIdx.x * blockDim.x + tid;
    if (b >= B) return;

    const float* __restrict__ vrow = values + (size_t)b * Td;
    float* __restrict__ srow = out + (size_t)b * Td;

    float h[Hd], c[Hd];
#pragma unroll
    for (int k = 0; k < Hd; k++) { h[k] = 0.f; c[k] = 0.f; }

#pragma unroll 1
    for (int t = 0; t < Td; t++) {
        // ---- MLP scoring head on pre-update h ----
        u64 hp[M1];
#pragma unroll
        for (int q = 0; q < M1; q++) hp[q] = pack2(h[2 * q], h[2 * q + 1]);

        float acc = sB2;
#pragma unroll
        for (int j = 0; j < M1; j++) {
            u64 a2 = *(const u64*)&sB1p[j];
#pragma unroll
            for (int q = 0; q < M1; q++) {
                const u64 w = *(const u64*)&sW1p[j][q];
                fma2(a2, hp[q], w);
            }
            float lo, hi; unpack2(a2, lo, hi);
            float z = lo + hi;
            z = fmaxf(z, 0.2f * z);              // leaky_relu(0.2)
            acc = fmaf(sW2[j], z, acc);
        }
        srow[t] = sig_acc(acc);

        // ---- LSTM gates, p-block at a time (only 4 u64 accumulators live) ----
        const float x = vrow[t];
        const u64 xp = pack2(x, x);
        float hn[Hd];
#pragma unroll
        for (int p = 0; p < 5; p++) {
            const ulonglong2* __restrict__ bx = (const ulonglong2*)sBX[p];
            const ulonglong2 bA = bx[0], bB = bx[1], wA = bx[2], wB = bx[3];
            u64 aI = fma2_3(xp, wA.x, bA.x);
            u64 aF = fma2_3(xp, wA.y, bA.y);
            u64 aG = fma2_3(xp, wB.x, bB.x);
            u64 aO = fma2_3(xp, wB.y, bB.y);

            const ulonglong2* __restrict__ wg = (const ulonglong2*)&sWg[p][0][0];
#pragma unroll
            for (int k = 0; k < Hd; k++) {
                const ulonglong2 wIF = wg[2 * k];      // LDS.128: i-pair, f-pair
                const ulonglong2 wGO = wg[2 * k + 1];  // LDS.128: g-pair, o-pair
                const u64 hk = pack2(h[k], h[k]);
                fma2(aI, hk, wIF.x); fma2(aF, hk, wIF.y);
                fma2(aG, hk, wGO.x); fma2(aO, hk, wGO.y);
            }

            float ia, ib, fa, fb, ga, gb, oa, ob;
            unpack2(aI, ia, ib); unpack2(aF, fa, fb);
            unpack2(aG, ga, gb); unpack2(aO, oa, ob);
            const float cnA = fmaf(sig_fast(fa), c[2 * p],     sig_fast(ia) * tanh_fast(ga));
            const float cnB = fmaf(sig_fast(fb), c[2 * p + 1], sig_fast(ib) * tanh_fast(gb));
            c[2 * p] = cnA; c[2 * p + 1] = cnB;
            hn[2 * p]     = sig_fast(oa) * tanh_fast(cnA);
            hn[2 * p + 1] = sig_fast(ob) * tanh_fast(cnB);
        }
#pragma unroll
        for (int k = 0; k < Hd; k++) h[k] = hn[k];
    }

    // ---- masks passthrough: one row = 20 floats = 5 float4 ----
    const float4* __restrict__ m0 = (const float4*)(masks + (size_t)b * Td);
    float4* __restrict__ mo = (float4*)(out + (size_t)B * Td + (size_t)b * Td);
#pragma unroll
    for (int q = 0; q < Td / 4; q++) mo[q] = m0[q];
}

extern "C" void kernel_launch(void* const* d_in, const int* in_sizes, int n_in,
                              void* d_out, int out_size)
{
    const float* values = (const float*)d_in[0];
    const float* masks  = (const float*)d_in[1];
    const float* W_ih   = (const float*)d_in[2];
    const float* W_hh   = (const float*)d_in[3];
    const float* b_ih   = (const float*)d_in[4];
    const float* b_hh   = (const float*)d_in[5];
    const float* W1     = (const float*)d_in[6];
    const float* b1     = (const float*)d_in[7];
    const float* W2     = (const float*)d_in[8];
    const float* b2     = (const float*)d_in[9];

    const int BT = in_sizes[0];          // B*T
    const int B  = BT / Td;
    float* out = (float*)d_out;

    lstm_disc_kernel<<<(B + 127) / 128, 128>>>(
        values, masks, W_ih, W_hh, b_ih, b_hh, W1, b1, W2, b2, out, B);
}